// round 2
// baseline (speedup 1.0000x reference)
#include <cuda_runtime.h>
#include <math.h>

#define B_      128
#define EMB_    256
#define NTOK    394     // 197 (p2r) + 197 (p1)
#define MTOK    (B_ * NTOK)          // 50432
#define MPE     (B_ * 196)           // 25088
#define SP      400                  // padded score row (394 -> 400)
#define SBATCH  (394 * SP)           // 157600 floats per (b,h)

// ---------------- scratch (static device globals; no runtime allocation) ---
__device__ float g_T1[MPE * 768];        // im2col for p=16
__device__ float g_T2[MPE * 192];        // im2col for p=8 (sampled patches)
__device__ float g_z [MTOK * EMB_];
__device__ float g_h [MTOK * EMB_];      // LN output; reused as proj tmp
__device__ float g_q [MTOK * EMB_];
__device__ float g_k [MTOK * EMB_];
__device__ float g_v [MTOK * EMB_];
__device__ float g_S [256 * SBATCH];     // scores, padded
__device__ float g_o [MTOK * EMB_];

// ---------------- im2col ---------------------------------------------------
// p1: patch 16, grid 14x14. T1 row = b*196 + (ph*14+pw), col k=(pi*16+pj)*3+c
__global__ void im2col1(const float* __restrict__ x, float* __restrict__ T) {
    int j = blockIdx.x, b = blockIdx.y;
    int ph = j / 14, pw = j % 14;
    const float* xb = x + (size_t)b * 3 * 224 * 224;
    float* Tr = T + ((size_t)b * 196 + j) * 768;
    for (int k = threadIdx.x; k < 768; k += 256) {
        int c = k % 3; int t2 = k / 3; int pj = t2 % 16; int pi = t2 / 16;
        Tr[k] = xb[(c * 224 + ph * 16 + pi) * 224 + pw * 16 + pj];
    }
}

// p2: patch 8, grid 28x28, but only patches jdx = 4*i+3 (i=0..195) are used.
__global__ void im2col2(const float* __restrict__ x, float* __restrict__ T) {
    int i = blockIdx.x, b = blockIdx.y;
    int jdx = 4 * i + 3;
    int ph = jdx / 28, pw = jdx % 28;
    const float* xb = x + (size_t)b * 3 * 224 * 224;
    float* Tr = T + ((size_t)b * 196 + i) * 192;
    int k = threadIdx.x;            // 192 threads
    int c = k % 3; int t2 = k / 3; int pj = t2 % 8; int pi = t2 / 8;
    Tr[k] = xb[(c * 224 + ph * 8 + pi) * 224 + pw * 8 + pj];
}

// cls tokens: z token 0 = cls2, token 197 = cls1
__global__ void cls_fill(const float* __restrict__ cls1,
                         const float* __restrict__ cls2,
                         float* __restrict__ z) {
    int b = blockIdx.x, e = threadIdx.x;
    z[((size_t)b * NTOK + 0)   * EMB_ + e] = cls2[e];
    z[((size_t)b * NTOK + 197) * EMB_ + e] = cls1[e];
}

// ---------------- generic 64x64x16 SGEMM, C = A@B + bias, epilogue modes ---
// mode 0: C[m*N+n]
// mode 1: patch-embed1 -> z token 198+j   (m = b*196 + j)
// mode 2: patch-embed2 -> z token 1+j
// mode 3: qkv layout   -> C[((b*2+h)*394+t)*128 + d]  (m = b*394+t, n = h*128+d)
__global__ __launch_bounds__(256)
void gemm64(const float* __restrict__ A, const float* __restrict__ B,
            const float* __restrict__ bias, float* __restrict__ C,
            int M, int N, int K, int mode) {
    __shared__ float As[16][68];
    __shared__ float Bs[16][68];
    int tid = threadIdx.x;
    int bm = blockIdx.y * 64, bn = blockIdx.x * 64;
    int lr = tid >> 2;              // 0..63
    int lc = (tid & 3) << 2;        // 0,4,8,12
    int brow = tid >> 4;            // 0..15
    int bcol = (tid & 15) << 2;     // 0..60
    int tx = tid & 15, ty = tid >> 4;
    float acc[4][4] = {};
    for (int k0 = 0; k0 < K; k0 += 16) {
        float4 a = *(const float4*)(A + (size_t)(bm + lr) * K + k0 + lc);
        As[lc + 0][lr] = a.x; As[lc + 1][lr] = a.y;
        As[lc + 2][lr] = a.z; As[lc + 3][lr] = a.w;
        float4 bb = *(const float4*)(B + (size_t)(k0 + brow) * N + bn + bcol);
        *(float4*)&Bs[brow][bcol] = bb;
        __syncthreads();
#pragma unroll
        for (int kk = 0; kk < 16; kk++) {
            float4 a4 = *(const float4*)&As[kk][ty * 4];
            float4 b4 = *(const float4*)&Bs[kk][tx * 4];
            float ar[4] = {a4.x, a4.y, a4.z, a4.w};
            float br[4] = {b4.x, b4.y, b4.z, b4.w};
#pragma unroll
            for (int i = 0; i < 4; i++)
#pragma unroll
                for (int j = 0; j < 4; j++)
                    acc[i][j] += ar[i] * br[j];
        }
        __syncthreads();
    }
#pragma unroll
    for (int i = 0; i < 4; i++) {
        int m = bm + ty * 4 + i;
#pragma unroll
        for (int j = 0; j < 4; j++) {
            int n = bn + tx * 4 + j;
            float val = acc[i][j] + bias[n];
            if (mode == 0) {
                C[(size_t)m * N + n] = val;
            } else if (mode == 1) {
                int b = m / 196, jj = m % 196;
                C[((size_t)b * NTOK + 198 + jj) * EMB_ + n] = val;
            } else if (mode == 2) {
                int b = m / 196, jj = m % 196;
                C[((size_t)b * NTOK + 1 + jj) * EMB_ + n] = val;
            } else {
                int b = m / NTOK, t = m % NTOK;
                int hh = n >> 7, d = n & 127;
                C[(((size_t)b * 2 + hh) * NTOK + t) * 128 + d] = val;
            }
        }
    }
}

// ---------------- layer norm (optionally residual-add) ---------------------
__global__ __launch_bounds__(256)
void ln_kernel(const float* __restrict__ in, const float* __restrict__ g,
               const float* __restrict__ b, float* __restrict__ out,
               const float* __restrict__ addsrc) {
    int r = blockIdx.x, e = threadIdx.x;
    size_t idx = (size_t)r * EMB_ + e;
    float v = in[idx];
    __shared__ float red[256];
    red[e] = v; __syncthreads();
    for (int s = 128; s > 0; s >>= 1) { if (e < s) red[e] += red[e + s]; __syncthreads(); }
    float mean = red[0] * (1.f / EMB_);
    __syncthreads();
    float d = v - mean;
    red[e] = d * d; __syncthreads();
    for (int s = 128; s > 0; s >>= 1) { if (e < s) red[e] += red[e + s]; __syncthreads(); }
    float var = red[0] * (1.f / EMB_);
    float nv = d * rsqrtf(var + 1e-5f) * g[e] + b[e];
    out[idx] = addsrc ? (addsrc[idx] + nv) : nv;
}

// ---------------- scores: S[bh][m][n] = Q[bh][m]·K[bh][n] ------------------
__global__ __launch_bounds__(256)
void gemm_nt(const float* __restrict__ Q, const float* __restrict__ Kt,
             float* __restrict__ S) {
    int bh = blockIdx.z;
    const float* Qb = Q + (size_t)bh * 394 * 128;
    const float* Kb = Kt + (size_t)bh * 394 * 128;
    float* Sb = S + (size_t)bh * SBATCH;
    __shared__ float As[16][68];
    __shared__ float Bs[16][68];
    int tid = threadIdx.x;
    int bm = blockIdx.y * 64, bn = blockIdx.x * 64;
    int lr = tid >> 2, lc = (tid & 3) << 2;
    int tx = tid & 15, ty = tid >> 4;
    float acc[4][4] = {};
    for (int k0 = 0; k0 < 128; k0 += 16) {
        int am = bm + lr;
        float4 a = (am < 394) ? *(const float4*)(Qb + (size_t)am * 128 + k0 + lc)
                              : make_float4(0.f, 0.f, 0.f, 0.f);
        As[lc + 0][lr] = a.x; As[lc + 1][lr] = a.y;
        As[lc + 2][lr] = a.z; As[lc + 3][lr] = a.w;
        int bnn = bn + lr;
        float4 bb = (bnn < 394) ? *(const float4*)(Kb + (size_t)bnn * 128 + k0 + lc)
                                : make_float4(0.f, 0.f, 0.f, 0.f);
        Bs[lc + 0][lr] = bb.x; Bs[lc + 1][lr] = bb.y;
        Bs[lc + 2][lr] = bb.z; Bs[lc + 3][lr] = bb.w;
        __syncthreads();
#pragma unroll
        for (int kk = 0; kk < 16; kk++) {
            float4 a4 = *(const float4*)&As[kk][ty * 4];
            float4 b4 = *(const float4*)&Bs[kk][tx * 4];
            float ar[4] = {a4.x, a4.y, a4.z, a4.w};
            float br[4] = {b4.x, b4.y, b4.z, b4.w};
#pragma unroll
            for (int i = 0; i < 4; i++)
#pragma unroll
                for (int j = 0; j < 4; j++)
                    acc[i][j] += ar[i] * br[j];
        }
        __syncthreads();
    }
#pragma unroll
    for (int i = 0; i < 4; i++) {
        int m = bm + ty * 4 + i;
        if (m >= 394) continue;
#pragma unroll
        for (int j = 0; j < 4; j++) {
            int n = bn + tx * 4 + j;
            if (n < 394) Sb[(size_t)m * SP + n] = acc[i][j];
        }
    }
}

// ---------------- softmax over last dim, then /16; zero the pad ------------
__global__ __launch_bounds__(128)
void softmax_div(float* __restrict__ S) {
    int q = blockIdx.x, bh = blockIdx.y, tid = threadIdx.x;
    float* row = S + (size_t)bh * SBATCH + (size_t)q * SP;
    __shared__ float red[128];
    float mx = -1e30f;
    for (int j = tid; j < 394; j += 128) mx = fmaxf(mx, row[j]);
    red[tid] = mx; __syncthreads();
    for (int s = 64; s > 0; s >>= 1) { if (tid < s) red[tid] = fmaxf(red[tid], red[tid + s]); __syncthreads(); }
    float M = red[0]; __syncthreads();
    float sum = 0.f;
    for (int j = tid; j < 394; j += 128) sum += expf(row[j] - M);
    red[tid] = sum; __syncthreads();
    for (int s = 64; s > 0; s >>= 1) { if (tid < s) red[tid] += red[tid + s]; __syncthreads(); }
    float inv = 1.f / (red[0] * 16.f);     // softmax / sqrt(EMB)
    for (int j = tid; j < 394; j += 128) row[j] = expf(row[j] - M) * inv;
    for (int j = 394 + tid; j < SP; j += 128) row[j] = 0.f;
}

// ---------------- PV: O[b][t][h*128+d] = sum_j P[bh][t][j] V[bh][j][d] -----
__global__ __launch_bounds__(256)
void gemm_pv(const float* __restrict__ S, const float* __restrict__ V,
             float* __restrict__ O) {
    int bh = blockIdx.z;
    int b = bh >> 1, hh = bh & 1;
    const float* Pb = S + (size_t)bh * SBATCH;
    const float* Vb = V + (size_t)bh * 394 * 128;
    float* Ob = O + (size_t)b * NTOK * EMB_ + hh * 128;
    __shared__ float As[16][68];
    __shared__ float Bs[16][68];
    int tid = threadIdx.x;
    int bm = blockIdx.y * 64, bn = blockIdx.x * 64;   // bn in {0,64}
    int lr = tid >> 2, lc = (tid & 3) << 2;
    int brow = tid >> 4, bcol = (tid & 15) << 2;
    int tx = tid & 15, ty = tid >> 4;
    float acc[4][4] = {};
    for (int k0 = 0; k0 < SP; k0 += 16) {             // pad cols are zero
        int am = bm + lr;
        float4 a = (am < 394) ? *(const float4*)(Pb + (size_t)am * SP + k0 + lc)
                              : make_float4(0.f, 0.f, 0.f, 0.f);
        As[lc + 0][lr] = a.x; As[lc + 1][lr] = a.y;
        As[lc + 2][lr] = a.z; As[lc + 3][lr] = a.w;
        int vr = k0 + brow;
        float4 bb = (vr < 394) ? *(const float4*)(Vb + (size_t)vr * 128 + bn + bcol)
                               : make_float4(0.f, 0.f, 0.f, 0.f);
        *(float4*)&Bs[brow][bcol] = bb;
        __syncthreads();
#pragma unroll
        for (int kk = 0; kk < 16; kk++) {
            float4 a4 = *(const float4*)&As[kk][ty * 4];
            float4 b4 = *(const float4*)&Bs[kk][tx * 4];
            float ar[4] = {a4.x, a4.y, a4.z, a4.w};
            float br[4] = {b4.x, b4.y, b4.z, b4.w};
#pragma unroll
            for (int i = 0; i < 4; i++)
#pragma unroll
                for (int j = 0; j < 4; j++)
                    acc[i][j] += ar[i] * br[j];
        }
        __syncthreads();
    }
#pragma unroll
    for (int i = 0; i < 4; i++) {
        int m = bm + ty * 4 + i;
        if (m >= 394) continue;
#pragma unroll
        for (int j = 0; j < 4; j++) {
            int n = bn + tx * 4 + j;                 // < 128
            Ob[(size_t)m * EMB_ + n] = acc[i][j];
        }
    }
}

// ---------------- head: mean-pool -> LN -> 256x2 -> log_softmax ------------
__global__ __launch_bounds__(256)
void head_kernel(const float* __restrict__ z, const float* __restrict__ g,
                 const float* __restrict__ bb, const float* __restrict__ Wc,
                 const float* __restrict__ bc, float* __restrict__ out) {
    int b = blockIdx.x, e = threadIdx.x;
    const float* zb = z + (size_t)b * NTOK * EMB_;
    float s = 0.f;
    for (int t = 0; t < NTOK; t++) s += zb[(size_t)t * EMB_ + e];
    float pooled = s * (1.f / NTOK);
    __shared__ float red[256];
    red[e] = pooled; __syncthreads();
    for (int st = 128; st > 0; st >>= 1) { if (e < st) red[e] += red[e + st]; __syncthreads(); }
    float mean = red[0] * (1.f / EMB_);
    __syncthreads();
    float d = pooled - mean;
    red[e] = d * d; __syncthreads();
    for (int st = 128; st > 0; st >>= 1) { if (e < st) red[e] += red[e + st]; __syncthreads(); }
    float var = red[0] * (1.f / EMB_);
    __syncthreads();
    float nv = d * rsqrtf(var + 1e-5f) * g[e] + bb[e];
    red[e] = nv * Wc[e * 2 + 0]; __syncthreads();
    for (int st = 128; st > 0; st >>= 1) { if (e < st) red[e] += red[e + st]; __syncthreads(); }
    float l0 = red[0] + bc[0];
    __syncthreads();
    red[e] = nv * Wc[e * 2 + 1]; __syncthreads();
    for (int st = 128; st > 0; st >>= 1) { if (e < st) red[e] += red[e + st]; __syncthreads(); }
    float l1 = red[0] + bc[1];
    if (e == 0) {
        float mx = fmaxf(l0, l1);
        float lse = mx + logf(expf(l0 - mx) + expf(l1 - mx));
        out[b * 2 + 0] = l0 - lse;
        out[b * 2 + 1] = l1 - lse;
    }
}

// ---------------- launch ----------------------------------------------------
extern "C" void kernel_launch(void* const* d_in, const int* in_sizes, int n_in,
                              void* d_out, int out_size) {
    const float* x     = (const float*)d_in[0];
    const float* W1    = (const float*)d_in[1];
    const float* b1    = (const float*)d_in[2];
    const float* cls1  = (const float*)d_in[3];
    const float* W2    = (const float*)d_in[4];
    const float* b2    = (const float*)d_in[5];
    const float* cls2  = (const float*)d_in[6];
    const float* ln1_g = (const float*)d_in[7];
    const float* ln1_b = (const float*)d_in[8];
    const float* Wq    = (const float*)d_in[9];
    const float* bq    = (const float*)d_in[10];
    const float* Wk    = (const float*)d_in[11];
    const float* bk    = (const float*)d_in[12];
    const float* Wv    = (const float*)d_in[13];
    const float* bv    = (const float*)d_in[14];
    const float* Wp    = (const float*)d_in[15];
    const float* bp    = (const float*)d_in[16];
    const float* ln2_g = (const float*)d_in[17];
    const float* ln2_b = (const float*)d_in[18];
    const float* lnc_g = (const float*)d_in[19];
    const float* lnc_b = (const float*)d_in[20];
    const float* Wc    = (const float*)d_in[21];
    const float* bc    = (const float*)d_in[22];
    float* out = (float*)d_out;

    float *T1, *T2, *z, *h, *q, *k, *v, *S, *o;
    cudaGetSymbolAddress((void**)&T1, g_T1);
    cudaGetSymbolAddress((void**)&T2, g_T2);
    cudaGetSymbolAddress((void**)&z,  g_z);
    cudaGetSymbolAddress((void**)&h,  g_h);
    cudaGetSymbolAddress((void**)&q,  g_q);
    cudaGetSymbolAddress((void**)&k,  g_k);
    cudaGetSymbolAddress((void**)&v,  g_v);
    cudaGetSymbolAddress((void**)&S,  g_S);
    cudaGetSymbolAddress((void**)&o,  g_o);

    im2col1<<<dim3(196, B_), 256>>>(x, T1);
    im2col2<<<dim3(196, B_), 192>>>(x, T2);
    cls_fill<<<B_, 256>>>(cls1, cls2, z);

    gemm64<<<dim3(4, MPE / 64), 256>>>(T1, W1, b1, z, MPE, 256, 768, 1);
    gemm64<<<dim3(4, MPE / 64), 256>>>(T2, W2, b2, z, MPE, 256, 192, 2);

    ln_kernel<<<MTOK, 256>>>(z, ln1_g, ln1_b, h, nullptr);

    gemm64<<<dim3(4, MTOK / 64), 256>>>(h, Wq, bq, q, MTOK, 256, 256, 3);
    gemm64<<<dim3(4, MTOK / 64), 256>>>(h, Wk, bk, k, MTOK, 256, 256, 3);
    gemm64<<<dim3(4, MTOK / 64), 256>>>(h, Wv, bv, v, MTOK, 256, 256, 3);

    gemm_nt<<<dim3(7, 7, 256), 256>>>(q, k, S);
    softmax_div<<<dim3(394, 256), 128>>>(S);
    gemm_pv<<<dim3(2, 7, 256), 256>>>(S, v, o);

    gemm64<<<dim3(4, MTOK / 64), 256>>>(o, Wp, bp, h, MTOK, 256, 256, 0);
    ln_kernel<<<MTOK, 256>>>(h, ln2_g, ln2_b, z, z);

    head_kernel<<<B_, 256>>>(z, lnc_g, lnc_b, Wc, bc, out);
}

// round 3
// speedup vs baseline: 2.2825x; 2.2825x over previous
#include <cuda_runtime.h>
#include <math.h>

#define B_      128
#define EMB_    256
#define NTOK    394
#define MTOK    (B_ * NTOK)          // 50432
#define MPE     (B_ * 196)           // 25088
#define SP      416                  // padded score row (394 -> 416, mult of 32)
#define SBATCH  (394 * SP)

// ---------------- scratch ---------------------------------------------------
__device__ float g_T1[MPE * 768];
__device__ float g_T2[MPE * 192];
__device__ float g_z [MTOK * EMB_];
__device__ float g_h [MTOK * EMB_];
__device__ float g_q [MTOK * EMB_];
__device__ float g_k [MTOK * EMB_];
__device__ float g_v [MTOK * EMB_];
__device__ float g_S [256 * SBATCH];
__device__ float g_o [MTOK * EMB_];

// ---------------- tf32 helpers ----------------------------------------------
__device__ __forceinline__ unsigned f2tf(float f) {
    unsigned u; asm("cvt.rna.tf32.f32 %0, %1;" : "=r"(u) : "f"(f)); return u;
}
__device__ __forceinline__ uint4 cvt4(float4 v) {
    uint4 o; o.x = f2tf(v.x); o.y = f2tf(v.y); o.z = f2tf(v.z); o.w = f2tf(v.w);
    return o;
}
__device__ __forceinline__ void mma8(float* acc, const unsigned* a, const unsigned* b) {
    asm volatile(
        "mma.sync.aligned.m16n8k8.row.col.f32.tf32.tf32.f32 "
        "{%0,%1,%2,%3}, {%4,%5,%6,%7}, {%8,%9}, {%0,%1,%2,%3};\n"
        : "+f"(acc[0]), "+f"(acc[1]), "+f"(acc[2]), "+f"(acc[3])
        : "r"(a[0]), "r"(a[1]), "r"(a[2]), "r"(a[3]), "r"(b[0]), "r"(b[1]));
}

// ---------------- im2col ----------------------------------------------------
__global__ void im2col1(const float* __restrict__ x, float* __restrict__ T) {
    int j = blockIdx.x, b = blockIdx.y;
    int ph = j / 14, pw = j % 14;
    const float* xb = x + (size_t)b * 3 * 224 * 224;
    float* Tr = T + ((size_t)b * 196 + j) * 768;
    for (int k = threadIdx.x; k < 768; k += 256) {
        int c = k % 3; int t2 = k / 3; int pj = t2 % 16; int pi = t2 / 16;
        Tr[k] = xb[(c * 224 + ph * 16 + pi) * 224 + pw * 16 + pj];
    }
}
__global__ void im2col2(const float* __restrict__ x, float* __restrict__ T) {
    int i = blockIdx.x, b = blockIdx.y;
    int jdx = 4 * i + 3;
    int ph = jdx / 28, pw = jdx % 28;
    const float* xb = x + (size_t)b * 3 * 224 * 224;
    float* Tr = T + ((size_t)b * 196 + i) * 192;
    int k = threadIdx.x;
    int c = k % 3; int t2 = k / 3; int pj = t2 % 8; int pi = t2 / 8;
    Tr[k] = xb[(c * 224 + ph * 8 + pi) * 224 + pw * 8 + pj];
}
__global__ void cls_fill(const float* __restrict__ cls1,
                         const float* __restrict__ cls2,
                         float* __restrict__ z) {
    int b = blockIdx.x, e = threadIdx.x;
    z[((size_t)b * NTOK + 0)   * EMB_ + e] = cls2[e];
    z[((size_t)b * NTOK + 197) * EMB_ + e] = cls1[e];
}

// ---------------- tf32 NN GEMM: C = A[MxK] @ B[KxN] + bias -------------------
// mode 0: plain C[m*N+n]      mode 1: patch1->z    mode 2: patch2->z
// mode 3: qkv layout          mode 4: PV (batched over blockIdx.z)
__global__ __launch_bounds__(256)
void gemm_nn(const float* __restrict__ A, const float* __restrict__ Bm,
             const float* __restrict__ bias, float* __restrict__ C,
             int M, int N, int K, int Kvalid, int mode) {
    __shared__ unsigned As[128 * 36];
    __shared__ unsigned Bs[32 * 72];
    int tid = threadIdx.x;
    int bm = blockIdx.y * 128, bn = blockIdx.x * 64;
    int wid = tid >> 5, lane = tid & 31;
    int wm = wid & 3, wn = wid >> 2;
    int gid = lane >> 2, tg = lane & 3;
    int z = blockIdx.z;
    if (mode == 4) {
        A  += (size_t)z * 394 * SP;
        Bm += (size_t)z * 394 * 128;
    }
    float4 ra[4]; float4 rb[2];
    float acc[2][4][4] = {};

    auto loadA = [&](int k0) {
#pragma unroll
        for (int i = 0; i < 4; i++) {
            int idx = tid + i * 256; int row = idx >> 3; int c4 = (idx & 7) << 2;
            int gm = bm + row;
            ra[i] = (gm < M) ? *(const float4*)(A + (size_t)gm * K + k0 + c4)
                             : make_float4(0.f, 0.f, 0.f, 0.f);
        }
    };
    auto loadB = [&](int k0) {
#pragma unroll
        for (int i = 0; i < 2; i++) {
            int idx = tid + i * 256; int kr = idx >> 4; int c4 = (idx & 15) << 2;
            rb[i] = (k0 + kr < Kvalid)
                  ? *(const float4*)(Bm + (size_t)(k0 + kr) * N + bn + c4)
                  : make_float4(0.f, 0.f, 0.f, 0.f);
        }
    };
    auto stsA = [&]() {
#pragma unroll
        for (int i = 0; i < 4; i++) {
            int idx = tid + i * 256; int row = idx >> 3; int c4 = (idx & 7) << 2;
            *(uint4*)&As[row * 36 + c4] = cvt4(ra[i]);
        }
    };
    auto stsB = [&]() {
#pragma unroll
        for (int i = 0; i < 2; i++) {
            int idx = tid + i * 256; int kr = idx >> 4; int c4 = (idx & 15) << 2;
            *(uint4*)&Bs[kr * 72 + c4] = cvt4(rb[i]);
        }
    };

    loadA(0); loadB(0);
    for (int k0 = 0; k0 < K; k0 += 32) {
        stsA(); stsB();
        __syncthreads();
        if (k0 + 32 < K) { loadA(k0 + 32); loadB(k0 + 32); }
#pragma unroll
        for (int kk = 0; kk < 32; kk += 8) {
            unsigned af[2][4], bf[4][2];
            int rb0 = wm * 32 + gid;
#pragma unroll
            for (int mt = 0; mt < 2; mt++) {
                int r = rb0 + mt * 16;
                af[mt][0] = As[r * 36 + kk + tg];
                af[mt][1] = As[(r + 8) * 36 + kk + tg];
                af[mt][2] = As[r * 36 + kk + tg + 4];
                af[mt][3] = As[(r + 8) * 36 + kk + tg + 4];
            }
#pragma unroll
            for (int nt = 0; nt < 4; nt++) {
                int c = wn * 32 + nt * 8 + gid;
                bf[nt][0] = Bs[(kk + tg) * 72 + c];
                bf[nt][1] = Bs[(kk + tg + 4) * 72 + c];
            }
#pragma unroll
            for (int mt = 0; mt < 2; mt++)
#pragma unroll
                for (int nt = 0; nt < 4; nt++)
                    mma8(acc[mt][nt], af[mt], bf[nt]);
        }
        __syncthreads();
    }

    // epilogue
#pragma unroll
    for (int mt = 0; mt < 2; mt++) {
#pragma unroll
        for (int nt = 0; nt < 4; nt++) {
            int n = bn + wn * 32 + nt * 8 + tg * 2;
            float bv0 = bias ? bias[n] : 0.f;
            float bv1 = bias ? bias[n + 1] : 0.f;
#pragma unroll
            for (int half = 0; half < 2; half++) {
                int m = bm + wm * 32 + mt * 16 + gid + half * 8;
                if (m >= M) continue;
                float v0 = acc[mt][nt][half * 2 + 0] + bv0;
                float v1 = acc[mt][nt][half * 2 + 1] + bv1;
                float2 val = make_float2(v0, v1);
                if (mode == 0) {
                    *(float2*)&C[(size_t)m * N + n] = val;
                } else if (mode == 1) {
                    int b = m / 196, jj = m % 196;
                    *(float2*)&C[((size_t)b * NTOK + 198 + jj) * EMB_ + n] = val;
                } else if (mode == 2) {
                    int b = m / 196, jj = m % 196;
                    *(float2*)&C[((size_t)b * NTOK + 1 + jj) * EMB_ + n] = val;
                } else if (mode == 3) {
                    int b = m / NTOK, t = m % NTOK;
                    int hh = n >> 7, d = n & 127;
                    *(float2*)&C[(((size_t)b * 2 + hh) * NTOK + t) * 128 + d] = val;
                } else {
                    int b = z >> 1, hh = z & 1;
                    *(float2*)&C[((size_t)b * NTOK + m) * EMB_ + hh * 128 + n] = val;
                }
            }
        }
    }
}

// ---------------- tf32 NT GEMM (scores): S = Q @ K^T, batched ----------------
__global__ __launch_bounds__(256)
void gemm_nt(const float* __restrict__ Q, const float* __restrict__ Kt,
             float* __restrict__ S) {
    __shared__ unsigned As[128 * 36];
    __shared__ unsigned Bs[64 * 36];
    int tid = threadIdx.x;
    int bm = blockIdx.y * 128, bn = blockIdx.x * 64;
    int z = blockIdx.z;
    const float* A  = Q  + (size_t)z * 394 * 128;
    const float* Bm = Kt + (size_t)z * 394 * 128;
    float* Sb = S + (size_t)z * SBATCH;
    int wid = tid >> 5, lane = tid & 31;
    int wm = wid & 3, wn = wid >> 2;
    int gid = lane >> 2, tg = lane & 3;
    float4 ra[4]; float4 rb[2];
    float acc[2][4][4] = {};

    auto loadA = [&](int k0) {
#pragma unroll
        for (int i = 0; i < 4; i++) {
            int idx = tid + i * 256; int row = idx >> 3; int c4 = (idx & 7) << 2;
            int gm = bm + row;
            ra[i] = (gm < 394) ? *(const float4*)(A + (size_t)gm * 128 + k0 + c4)
                               : make_float4(0.f, 0.f, 0.f, 0.f);
        }
    };
    auto loadB = [&](int k0) {
#pragma unroll
        for (int i = 0; i < 2; i++) {
            int idx = tid + i * 256; int row = idx >> 3; int c4 = (idx & 7) << 2;
            int gn = bn + row;
            rb[i] = (gn < 394) ? *(const float4*)(Bm + (size_t)gn * 128 + k0 + c4)
                               : make_float4(0.f, 0.f, 0.f, 0.f);
        }
    };
    auto stsA = [&]() {
#pragma unroll
        for (int i = 0; i < 4; i++) {
            int idx = tid + i * 256; int row = idx >> 3; int c4 = (idx & 7) << 2;
            *(uint4*)&As[row * 36 + c4] = cvt4(ra[i]);
        }
    };
    auto stsB = [&]() {
#pragma unroll
        for (int i = 0; i < 2; i++) {
            int idx = tid + i * 256; int row = idx >> 3; int c4 = (idx & 7) << 2;
            *(uint4*)&Bs[row * 36 + c4] = cvt4(rb[i]);
        }
    };

    loadA(0); loadB(0);
    for (int k0 = 0; k0 < 128; k0 += 32) {
        stsA(); stsB();
        __syncthreads();
        if (k0 + 32 < 128) { loadA(k0 + 32); loadB(k0 + 32); }
#pragma unroll
        for (int kk = 0; kk < 32; kk += 8) {
            unsigned af[2][4], bf[4][2];
            int rb0 = wm * 32 + gid;
#pragma unroll
            for (int mt = 0; mt < 2; mt++) {
                int r = rb0 + mt * 16;
                af[mt][0] = As[r * 36 + kk + tg];
                af[mt][1] = As[(r + 8) * 36 + kk + tg];
                af[mt][2] = As[r * 36 + kk + tg + 4];
                af[mt][3] = As[(r + 8) * 36 + kk + tg + 4];
            }
#pragma unroll
            for (int nt = 0; nt < 4; nt++) {
                int c = wn * 32 + nt * 8 + gid;
                bf[nt][0] = Bs[c * 36 + kk + tg];
                bf[nt][1] = Bs[c * 36 + kk + tg + 4];
            }
#pragma unroll
            for (int mt = 0; mt < 2; mt++)
#pragma unroll
                for (int nt = 0; nt < 4; nt++)
                    mma8(acc[mt][nt], af[mt], bf[nt]);
        }
        __syncthreads();
    }

#pragma unroll
    for (int mt = 0; mt < 2; mt++)
#pragma unroll
        for (int nt = 0; nt < 4; nt++) {
            int n = bn + wn * 32 + nt * 8 + tg * 2;
            if (n >= 394) continue;
#pragma unroll
            for (int half = 0; half < 2; half++) {
                int m = bm + wm * 32 + mt * 16 + gid + half * 8;
                if (m >= 394) continue;
                *(float2*)&Sb[(size_t)m * SP + n] =
                    make_float2(acc[mt][nt][half * 2], acc[mt][nt][half * 2 + 1]);
            }
        }
}

// ---------------- layer norm (shuffle reductions, optional residual) --------
__global__ __launch_bounds__(256)
void ln_kernel(const float* __restrict__ in, const float* __restrict__ g,
               const float* __restrict__ b, float* __restrict__ out,
               const float* __restrict__ addsrc) {
    int r = blockIdx.x, e = threadIdx.x;
    size_t idx = (size_t)r * EMB_ + e;
    float v = in[idx];
    float s = v, s2 = v * v;
#pragma unroll
    for (int off = 16; off > 0; off >>= 1) {
        s  += __shfl_xor_sync(0xffffffff, s,  off);
        s2 += __shfl_xor_sync(0xffffffff, s2, off);
    }
    __shared__ float ss[8], ss2[8];
    if ((e & 31) == 0) { ss[e >> 5] = s; ss2[e >> 5] = s2; }
    __syncthreads();
    float tot = 0.f, tot2 = 0.f;
#pragma unroll
    for (int i = 0; i < 8; i++) { tot += ss[i]; tot2 += ss2[i]; }
    float mean = tot * (1.f / EMB_);
    float var = tot2 * (1.f / EMB_) - mean * mean;
    float nv = (v - mean) * rsqrtf(var + 1e-5f) * g[e] + b[e];
    out[idx] = addsrc ? (addsrc[idx] + nv) : nv;
}

// ---------------- softmax (register-cached), /16, zero-fill pad -------------
__global__ __launch_bounds__(128)
void softmax_div(float* __restrict__ S) {
    int q = blockIdx.x, bh = blockIdx.y, tid = threadIdx.x;
    float* row = S + (size_t)bh * SBATCH + (size_t)q * SP;
    float v[4]; float mx = -1e30f;
#pragma unroll
    for (int i = 0; i < 4; i++) {
        int j = tid + i * 128;
        v[i] = (j < 394) ? row[j] : -1e30f;
        mx = fmaxf(mx, v[i]);
    }
#pragma unroll
    for (int off = 16; off > 0; off >>= 1)
        mx = fmaxf(mx, __shfl_xor_sync(0xffffffff, mx, off));
    __shared__ float sm[4], sv[4];
    if ((tid & 31) == 0) sm[tid >> 5] = mx;
    __syncthreads();
    float M = fmaxf(fmaxf(sm[0], sm[1]), fmaxf(sm[2], sm[3]));
    float sum = 0.f;
#pragma unroll
    for (int i = 0; i < 4; i++) {
        v[i] = (tid + i * 128 < 394) ? __expf(v[i] - M) : 0.f;
        sum += v[i];
    }
#pragma unroll
    for (int off = 16; off > 0; off >>= 1)
        sum += __shfl_xor_sync(0xffffffff, sum, off);
    if ((tid & 31) == 0) sv[tid >> 5] = sum;
    __syncthreads();
    float inv = 1.f / ((sv[0] + sv[1] + sv[2] + sv[3]) * 16.f);
#pragma unroll
    for (int i = 0; i < 4; i++) {
        int j = tid + i * 128;
        if (j < 394) row[j] = v[i] * inv;
    }
    if (tid < SP - 394) row[394 + tid] = 0.f;
}

// ---------------- head -------------------------------------------------------
__global__ __launch_bounds__(256)
void head_kernel(const float* __restrict__ z, const float* __restrict__ g,
                 const float* __restrict__ bb, const float* __restrict__ Wc,
                 const float* __restrict__ bc, float* __restrict__ out) {
    int b = blockIdx.x, e = threadIdx.x;
    const float* zb = z + (size_t)b * NTOK * EMB_;
    float s = 0.f;
    for (int t = 0; t < NTOK; t++) s += zb[(size_t)t * EMB_ + e];
    float pooled = s * (1.f / NTOK);
    __shared__ float red[256];
    red[e] = pooled; __syncthreads();
    for (int st = 128; st > 0; st >>= 1) { if (e < st) red[e] += red[e + st]; __syncthreads(); }
    float mean = red[0] * (1.f / EMB_);
    __syncthreads();
    float d = pooled - mean;
    red[e] = d * d; __syncthreads();
    for (int st = 128; st > 0; st >>= 1) { if (e < st) red[e] += red[e + st]; __syncthreads(); }
    float var = red[0] * (1.f / EMB_);
    __syncthreads();
    float nv = d * rsqrtf(var + 1e-5f) * g[e] + bb[e];
    red[e] = nv * Wc[e * 2 + 0]; __syncthreads();
    for (int st = 128; st > 0; st >>= 1) { if (e < st) red[e] += red[e + st]; __syncthreads(); }
    float l0 = red[0] + bc[0];
    __syncthreads();
    red[e] = nv * Wc[e * 2 + 1]; __syncthreads();
    for (int st = 128; st > 0; st >>= 1) { if (e < st) red[e] += red[e + st]; __syncthreads(); }
    float l1 = red[0] + bc[1];
    if (e == 0) {
        float mx = fmaxf(l0, l1);
        float lse = mx + logf(expf(l0 - mx) + expf(l1 - mx));
        out[b * 2 + 0] = l0 - lse;
        out[b * 2 + 1] = l1 - lse;
    }
}

// ---------------- launch ------------------------------------------------------
extern "C" void kernel_launch(void* const* d_in, const int* in_sizes, int n_in,
                              void* d_out, int out_size) {
    const float* x     = (const float*)d_in[0];
    const float* W1    = (const float*)d_in[1];
    const float* b1    = (const float*)d_in[2];
    const float* cls1  = (const float*)d_in[3];
    const float* W2    = (const float*)d_in[4];
    const float* b2    = (const float*)d_in[5];
    const float* cls2  = (const float*)d_in[6];
    const float* ln1_g = (const float*)d_in[7];
    const float* ln1_b = (const float*)d_in[8];
    const float* Wq    = (const float*)d_in[9];
    const float* bq    = (const float*)d_in[10];
    const float* Wk    = (const float*)d_in[11];
    const float* bk    = (const float*)d_in[12];
    const float* Wv    = (const float*)d_in[13];
    const float* bv    = (const float*)d_in[14];
    const float* Wp    = (const float*)d_in[15];
    const float* bp    = (const float*)d_in[16];
    const float* ln2_g = (const float*)d_in[17];
    const float* ln2_b = (const float*)d_in[18];
    const float* lnc_g = (const float*)d_in[19];
    const float* lnc_b = (const float*)d_in[20];
    const float* Wc    = (const float*)d_in[21];
    const float* bc    = (const float*)d_in[22];
    float* out = (float*)d_out;

    float *T1, *T2, *z, *h, *q, *k, *v, *S, *o;
    cudaGetSymbolAddress((void**)&T1, g_T1);
    cudaGetSymbolAddress((void**)&T2, g_T2);
    cudaGetSymbolAddress((void**)&z,  g_z);
    cudaGetSymbolAddress((void**)&h,  g_h);
    cudaGetSymbolAddress((void**)&q,  g_q);
    cudaGetSymbolAddress((void**)&k,  g_k);
    cudaGetSymbolAddress((void**)&v,  g_v);
    cudaGetSymbolAddress((void**)&S,  g_S);
    cudaGetSymbolAddress((void**)&o,  g_o);

    im2col1<<<dim3(196, B_), 256>>>(x, T1);
    im2col2<<<dim3(196, B_), 192>>>(x, T2);
    cls_fill<<<B_, 256>>>(cls1, cls2, z);

    gemm_nn<<<dim3(4, 196), 256>>>(T1, W1, b1, z, MPE, 256, 768, 768, 1);
    gemm_nn<<<dim3(4, 196), 256>>>(T2, W2, b2, z, MPE, 256, 192, 192, 2);

    ln_kernel<<<MTOK, 256>>>(z, ln1_g, ln1_b, h, nullptr);

    gemm_nn<<<dim3(4, 394), 256>>>(h, Wq, bq, q, MTOK, 256, 256, 256, 3);
    gemm_nn<<<dim3(4, 394), 256>>>(h, Wk, bk, k, MTOK, 256, 256, 256, 3);
    gemm_nn<<<dim3(4, 394), 256>>>(h, Wv, bv, v, MTOK, 256, 256, 256, 3);

    gemm_nt<<<dim3(7, 4, 256), 256>>>(q, k, S);
    softmax_div<<<dim3(394, 256), 128>>>(S);
    gemm_nn<<<dim3(2, 4, 256), 256>>>(S, v, nullptr, o, 394, 128, SP, 394, 4);

    gemm_nn<<<dim3(4, 394), 256>>>(o, Wp, bp, h, MTOK, 256, 256, 256, 0);
    ln_kernel<<<MTOK, 256>>>(h, ln2_g, ln2_b, z, z);

    head_kernel<<<B_, 256>>>(z, lnc_g, lnc_b, Wc, bc, out);
}

// round 4
// speedup vs baseline: 2.8277x; 1.2389x over previous
#include <cuda_runtime.h>
#include <math.h>

#define B_      128
#define EMB_    256
#define NTOK    394
#define MTOK    (B_ * NTOK)          // 50432
#define MPE     (B_ * 196)           // 25088
#define SP      416                  // padded score row
#define SBATCH  (394 * SP)

#define KC      32
#define STG     3
#define ASTR    36                   // A smem row stride (floats)
#define BSTR    136                  // B smem row stride (floats)
#define SMEM_NN ((STG * (128 * ASTR + 32 * BSTR)) * 4)   // 107520 B
#define SMEM_NT ((STG * (128 * ASTR + 128 * ASTR)) * 4)  // 110592 B

// ---------------- scratch ---------------------------------------------------
__device__ float g_T1[MPE * 768];
__device__ float g_T2[MPE * 192];
__device__ float g_Wt[507904];       // tf32-rounded weights, concatenated
__device__ float g_z [MTOK * EMB_];
__device__ float g_h [MTOK * EMB_];
__device__ float g_q [MTOK * EMB_];
__device__ float g_k [MTOK * EMB_];
__device__ float g_v [MTOK * EMB_];
__device__ float g_S [256 * SBATCH];
__device__ float g_o [MTOK * EMB_];

// weight offsets in g_Wt
#define OFF_W1 0
#define OFF_W2 196608
#define OFF_WQ 245760
#define OFF_WK 311296
#define OFF_WV 376832
#define OFF_WP 442368

// ---------------- helpers ----------------------------------------------------
__device__ __forceinline__ float f2tf_f(float f) {
    unsigned u; asm("cvt.rna.tf32.f32 %0, %1;" : "=r"(u) : "f"(f));
    return __uint_as_float(u);
}
__device__ __forceinline__ void mma8(float* acc, const unsigned* a, const unsigned* b) {
    asm volatile(
        "mma.sync.aligned.m16n8k8.row.col.f32.tf32.tf32.f32 "
        "{%0,%1,%2,%3}, {%4,%5,%6,%7}, {%8,%9}, {%0,%1,%2,%3};\n"
        : "+f"(acc[0]), "+f"(acc[1]), "+f"(acc[2]), "+f"(acc[3])
        : "r"(a[0]), "r"(a[1]), "r"(a[2]), "r"(a[3]), "r"(b[0]), "r"(b[1]));
}
__device__ __forceinline__ void cpa16(float* dst, const float* src, bool pred) {
    unsigned d = (unsigned)__cvta_generic_to_shared(dst);
    const float* s = pred ? src : dst == 0 ? src : src;  // keep src valid
    int sz = pred ? 16 : 0;
    asm volatile("cp.async.cg.shared.global [%0], [%1], 16, %2;\n"
                 :: "r"(d), "l"(s), "r"(sz));
}
__device__ __forceinline__ void cpa_commit() { asm volatile("cp.async.commit_group;\n"); }
template <int N>
__device__ __forceinline__ void cpa_wait() { asm volatile("cp.async.wait_group %0;\n" :: "n"(N)); }

// ---------------- weight prep: round all GEMM weights to tf32 once ----------
__global__ void prep_w(const float* __restrict__ W1, const float* __restrict__ W2,
                       const float* __restrict__ Wq, const float* __restrict__ Wk,
                       const float* __restrict__ Wv, const float* __restrict__ Wp,
                       float* __restrict__ out) {
    int i = blockIdx.x * 256 + threadIdx.x;     // < 507904
    const float* src; int j;
    if (i < OFF_W2)      { src = W1; j = i; }
    else if (i < OFF_WQ) { src = W2; j = i - OFF_W2; }
    else if (i < OFF_WK) { src = Wq; j = i - OFF_WQ; }
    else if (i < OFF_WV) { src = Wk; j = i - OFF_WK; }
    else if (i < OFF_WP) { src = Wv; j = i - OFF_WV; }
    else                 { src = Wp; j = i - OFF_WP; }
    out[i] = f2tf_f(src[j]);
}

// ---------------- im2col (smem-staged, tf32-rounded output) -----------------
__global__ void im2col1(const float* __restrict__ x, float* __restrict__ T) {
    __shared__ float buf[768];
    int j = blockIdx.x, b = blockIdx.y;
    int ph = j / 14, pw = j % 14;
    const float* xb = x + (size_t)b * 3 * 224 * 224 + (size_t)(ph * 16) * 224 + pw * 16;
    int t = threadIdx.x;                 // 256
    int pi = t >> 4, pj = t & 15;
#pragma unroll
    for (int c = 0; c < 3; c++)
        buf[(pi * 16 + pj) * 3 + c] = f2tf_f(xb[((size_t)c * 224 + pi) * 224 + pj]);
    __syncthreads();
    float* Tr = T + ((size_t)b * 196 + j) * 768;
#pragma unroll
    for (int k = 0; k < 3; k++) Tr[t + k * 256] = buf[t + k * 256];
}
__global__ void im2col2(const float* __restrict__ x, float* __restrict__ T) {
    __shared__ float buf[192];
    int i = blockIdx.x, b = blockIdx.y;
    int jdx = 4 * i + 3;
    int ph = jdx / 28, pw = jdx % 28;
    const float* xb = x + (size_t)b * 3 * 224 * 224 + (size_t)(ph * 8) * 224 + pw * 8;
    int t = threadIdx.x;                 // 192
    int c = t >> 6, pos = t & 63;
    int pi = pos >> 3, pj = pos & 7;
    buf[pos * 3 + c] = f2tf_f(xb[((size_t)c * 224 + pi) * 224 + pj]);
    __syncthreads();
    T[((size_t)b * 196 + i) * 192 + t] = buf[t];
}
__global__ void cls_fill(const float* __restrict__ cls1,
                         const float* __restrict__ cls2,
                         float* __restrict__ z) {
    int b = blockIdx.x, e = threadIdx.x;
    z[((size_t)b * NTOK + 0)   * EMB_ + e] = cls2[e];
    z[((size_t)b * NTOK + 197) * EMB_ + e] = cls1[e];
}

// ---------------- NN GEMM: cp.async 3-stage, 128x128 tile, tf32 mma ---------
// mode 0: plain (no cvt)  1: patch1->z  2: patch2->z  3: qkv (cvt)  4: PV (cvt)
__global__ __launch_bounds__(256)
void gemm_nn(const float* __restrict__ A, const float* __restrict__ Bm,
             const float* __restrict__ bias, float* __restrict__ C,
             int M, int N, int K, int Kvalid, int mode) {
    extern __shared__ float smem[];
    float* As = smem;                          // [STG][128][ASTR]
    float* Bs = smem + STG * 128 * ASTR;       // [STG][32][BSTR]
    int tid = threadIdx.x;
    int bm = blockIdx.y * 128, bn = blockIdx.x * 128;
    int wid = tid >> 5, lane = tid & 31;
    int wm = wid & 3, wn = wid >> 2;           // warp tile 32x64
    int gid = lane >> 2, tg = lane & 3;
    int zb = blockIdx.z;
    if (mode == 4) { A += (size_t)zb * 394 * SP; Bm += (size_t)zb * 394 * 128; }

    int aRow = tid >> 3, aC4 = (tid & 7) << 2;        // +i*32 rows
    int bKr  = tid >> 6, bC4 = (tid & 63) << 1;       // hmm — recompute below
    (void)bKr; (void)bC4;

    auto loadA = [&](int s, int k0) {
        float* dst = As + s * 128 * ASTR;
#pragma unroll
        for (int i = 0; i < 4; i++) {
            int row = aRow + i * 32;
            bool p = (bm + row) < M;
            const float* src = A + (size_t)(p ? bm + row : bm) * K + k0 + aC4;
            cpa16(dst + row * ASTR + aC4, src, p);
        }
    };
    int kRow = tid >> 5, kC4 = (lane) << 2;           // 32 floats... per-row chunks
    auto loadB = [&](int s, int k0) {
        float* dst = Bs + s * 32 * BSTR;
#pragma unroll
        for (int i = 0; i < 4; i++) {
            int idx = tid + i * 256;
            int kr = idx >> 5, c4 = (idx & 31) << 2;  // 32 rows x 128 cols
            bool p = (k0 + kr) < Kvalid;
            const float* src = Bm + (size_t)(p ? k0 + kr : 0) * N + bn + c4;
            cpa16(dst + kr * BSTR + c4, src, p);
        }
    };
    (void)kRow; (void)kC4;

    float acc[2][8][4] = {};
    int nk = K / KC;
#pragma unroll
    for (int s = 0; s < STG - 1; s++) { loadA(s, s * KC); loadB(s, s * KC); cpa_commit(); }

    for (int it = 0; it < nk; it++) {
        cpa_wait<STG - 2>();
        __syncthreads();
        int nxt = it + STG - 1;
        if (nxt < nk) { loadA(nxt % STG, nxt * KC); loadB(nxt % STG, nxt * KC); }
        cpa_commit();
        int s = it % STG;
        const float* ap = As + s * 128 * ASTR + (wm * 32 + gid) * ASTR + tg;
        const float* bp = Bs + s * 32 * BSTR + tg * BSTR + wn * 64 + gid;
#pragma unroll
        for (int kk = 0; kk < KC; kk += 8) {
            unsigned af[2][4], bf[8][2];
#pragma unroll
            for (int mt = 0; mt < 2; mt++) {
                af[mt][0] = __float_as_uint(ap[mt * 16 * ASTR + kk]);
                af[mt][1] = __float_as_uint(ap[(mt * 16 + 8) * ASTR + kk]);
                af[mt][2] = __float_as_uint(ap[mt * 16 * ASTR + kk + 4]);
                af[mt][3] = __float_as_uint(ap[(mt * 16 + 8) * ASTR + kk + 4]);
            }
#pragma unroll
            for (int nt = 0; nt < 8; nt++) {
                bf[nt][0] = __float_as_uint(bp[kk * BSTR + nt * 8]);
                bf[nt][1] = __float_as_uint(bp[(kk + 4) * BSTR + nt * 8]);
            }
#pragma unroll
            for (int mt = 0; mt < 2; mt++)
#pragma unroll
                for (int nt = 0; nt < 8; nt++)
                    mma8(acc[mt][nt], af[mt], bf[nt]);
        }
        __syncthreads();
    }

#pragma unroll
    for (int mt = 0; mt < 2; mt++) {
#pragma unroll
        for (int nt = 0; nt < 8; nt++) {
            int n = bn + wn * 64 + nt * 8 + tg * 2;
            float bv0 = bias ? bias[n] : 0.f;
            float bv1 = bias ? bias[n + 1] : 0.f;
#pragma unroll
            for (int half = 0; half < 2; half++) {
                int m = bm + wm * 32 + mt * 16 + gid + half * 8;
                if (m >= M) continue;
                float v0 = acc[mt][nt][half * 2 + 0] + bv0;
                float v1 = acc[mt][nt][half * 2 + 1] + bv1;
                if (mode >= 3) { v0 = f2tf_f(v0); v1 = f2tf_f(v1); }
                float2 val = make_float2(v0, v1);
                if (mode == 0) {
                    *(float2*)&C[(size_t)m * N + n] = val;
                } else if (mode == 1) {
                    int b = m / 196, jj = m % 196;
                    *(float2*)&C[((size_t)b * NTOK + 198 + jj) * EMB_ + n] = val;
                } else if (mode == 2) {
                    int b = m / 196, jj = m % 196;
                    *(float2*)&C[((size_t)b * NTOK + 1 + jj) * EMB_ + n] = val;
                } else if (mode == 3) {
                    int b = m / NTOK, t = m % NTOK;
                    int hh = n >> 7, d = n & 127;
                    *(float2*)&C[(((size_t)b * 2 + hh) * NTOK + t) * 128 + d] = val;
                } else {
                    int b = zb >> 1, hh = zb & 1;
                    *(float2*)&C[((size_t)b * NTOK + m) * EMB_ + hh * 128 + n] = val;
                }
            }
        }
    }
}

// ---------------- NT GEMM (scores): S = Q @ K^T, batched ---------------------
__global__ __launch_bounds__(256)
void gemm_nt(const float* __restrict__ Q, const float* __restrict__ Kt,
             float* __restrict__ S) {
    extern __shared__ float smem[];
    float* As = smem;                          // [STG][128][ASTR]
    float* Bs = smem + STG * 128 * ASTR;       // [STG][128][ASTR]
    int tid = threadIdx.x;
    int bm = blockIdx.y * 128, bn = blockIdx.x * 128;
    int zb = blockIdx.z;
    const float* A  = Q  + (size_t)zb * 394 * 128;
    const float* Bm = Kt + (size_t)zb * 394 * 128;
    float* Sb = S + (size_t)zb * SBATCH;
    int wid = tid >> 5, lane = tid & 31;
    int wm = wid & 3, wn = wid >> 2;
    int gid = lane >> 2, tg = lane & 3;
    int aRow = tid >> 3, aC4 = (tid & 7) << 2;

    auto loadT = [&](float* dstBase, const float* src0, int base, int k0) {
#pragma unroll
        for (int i = 0; i < 4; i++) {
            int row = aRow + i * 32;
            bool p = (base + row) < 394;
            const float* src = src0 + (size_t)(p ? base + row : 0) * 128 + k0 + aC4;
            cpa16(dstBase + row * ASTR + aC4, src, p);
        }
    };

    float acc[2][8][4] = {};
#pragma unroll
    for (int s = 0; s < STG - 1; s++) {
        loadT(As + s * 128 * ASTR, A, bm, s * KC);
        loadT(Bs + s * 128 * ASTR, Bm, bn, s * KC);
        cpa_commit();
    }
    int nk = 128 / KC;   // 4
    for (int it = 0; it < nk; it++) {
        cpa_wait<STG - 2>();
        __syncthreads();
        int nxt = it + STG - 1;
        if (nxt < nk) {
            loadT(As + (nxt % STG) * 128 * ASTR, A, bm, nxt * KC);
            loadT(Bs + (nxt % STG) * 128 * ASTR, Bm, bn, nxt * KC);
        }
        cpa_commit();
        int s = it % STG;
        const float* ap = As + s * 128 * ASTR + (wm * 32 + gid) * ASTR + tg;
        const float* bp = Bs + s * 128 * ASTR + (wn * 64 + gid) * ASTR + tg;
#pragma unroll
        for (int kk = 0; kk < KC; kk += 8) {
            unsigned af[2][4], bf[8][2];
#pragma unroll
            for (int mt = 0; mt < 2; mt++) {
                af[mt][0] = __float_as_uint(ap[mt * 16 * ASTR + kk]);
                af[mt][1] = __float_as_uint(ap[(mt * 16 + 8) * ASTR + kk]);
                af[mt][2] = __float_as_uint(ap[mt * 16 * ASTR + kk + 4]);
                af[mt][3] = __float_as_uint(ap[(mt * 16 + 8) * ASTR + kk + 4]);
            }
#pragma unroll
            for (int nt = 0; nt < 8; nt++) {
                bf[nt][0] = __float_as_uint(bp[nt * 8 * ASTR + kk]);
                bf[nt][1] = __float_as_uint(bp[nt * 8 * ASTR + kk + 4]);
            }
#pragma unroll
            for (int mt = 0; mt < 2; mt++)
#pragma unroll
                for (int nt = 0; nt < 8; nt++)
                    mma8(acc[mt][nt], af[mt], bf[nt]);
        }
        __syncthreads();
    }
#pragma unroll
    for (int mt = 0; mt < 2; mt++)
#pragma unroll
        for (int nt = 0; nt < 8; nt++) {
            int n = bn + wn * 64 + nt * 8 + tg * 2;
            if (n >= 394) continue;
#pragma unroll
            for (int half = 0; half < 2; half++) {
                int m = bm + wm * 32 + mt * 16 + gid + half * 8;
                if (m >= 394) continue;
                *(float2*)&Sb[(size_t)m * SP + n] =
                    make_float2(acc[mt][nt][half * 2], acc[mt][nt][half * 2 + 1]);
            }
        }
}

// ---------------- layer norm (tf32-rounds output when docvt) ----------------
__global__ __launch_bounds__(256)
void ln_kernel(const float* __restrict__ in, const float* __restrict__ g,
               const float* __restrict__ b, float* __restrict__ out,
               const float* __restrict__ addsrc, int docvt) {
    int r = blockIdx.x, e = threadIdx.x;
    size_t idx = (size_t)r * EMB_ + e;
    float v = in[idx];
    float s = v, s2 = v * v;
#pragma unroll
    for (int off = 16; off > 0; off >>= 1) {
        s  += __shfl_xor_sync(0xffffffff, s,  off);
        s2 += __shfl_xor_sync(0xffffffff, s2, off);
    }
    __shared__ float ss[8], ss2[8];
    if ((e & 31) == 0) { ss[e >> 5] = s; ss2[e >> 5] = s2; }
    __syncthreads();
    float tot = 0.f, tot2 = 0.f;
#pragma unroll
    for (int i = 0; i < 8; i++) { tot += ss[i]; tot2 += ss2[i]; }
    float mean = tot * (1.f / EMB_);
    float var = tot2 * (1.f / EMB_) - mean * mean;
    float nv = (v - mean) * rsqrtf(var + 1e-5f) * g[e] + b[e];
    if (docvt) nv = f2tf_f(nv);
    out[idx] = addsrc ? (addsrc[idx] + nv) : nv;
}

// ---------------- softmax, /16, tf32-round, zero-fill pad -------------------
__global__ __launch_bounds__(128)
void softmax_div(float* __restrict__ S) {
    int q = blockIdx.x, bh = blockIdx.y, tid = threadIdx.x;
    float* row = S + (size_t)bh * SBATCH + (size_t)q * SP;
    float v[4]; float mx = -1e30f;
#pragma unroll
    for (int i = 0; i < 4; i++) {
        int j = tid + i * 128;
        v[i] = (j < 394) ? row[j] : -1e30f;
        mx = fmaxf(mx, v[i]);
    }
#pragma unroll
    for (int off = 16; off > 0; off >>= 1)
        mx = fmaxf(mx, __shfl_xor_sync(0xffffffff, mx, off));
    __shared__ float sm[4], sv[4];
    if ((tid & 31) == 0) sm[tid >> 5] = mx;
    __syncthreads();
    float M = fmaxf(fmaxf(sm[0], sm[1]), fmaxf(sm[2], sm[3]));
    float sum = 0.f;
#pragma unroll
    for (int i = 0; i < 4; i++) {
        v[i] = (tid + i * 128 < 394) ? __expf(v[i] - M) : 0.f;
        sum += v[i];
    }
#pragma unroll
    for (int off = 16; off > 0; off >>= 1)
        sum += __shfl_xor_sync(0xffffffff, sum, off);
    if ((tid & 31) == 0) sv[tid >> 5] = sum;
    __syncthreads();
    float inv = 1.f / ((sv[0] + sv[1] + sv[2] + sv[3]) * 16.f);
#pragma unroll
    for (int i = 0; i < 4; i++) {
        int j = tid + i * 128;
        if (j < 394) row[j] = f2tf_f(v[i] * inv);
    }
    if (tid < SP - 394) row[394 + tid] = 0.f;
}

// ---------------- head -------------------------------------------------------
__global__ __launch_bounds__(256)
void head_kernel(const float* __restrict__ z, const float* __restrict__ g,
                 const float* __restrict__ bb, const float* __restrict__ Wc,
                 const float* __restrict__ bc, float* __restrict__ out) {
    int b = blockIdx.x, e = threadIdx.x;
    const float* zb = z + (size_t)b * NTOK * EMB_;
    float s = 0.f;
    for (int t = 0; t < NTOK; t++) s += zb[(size_t)t * EMB_ + e];
    float pooled = s * (1.f / NTOK);
    __shared__ float red[256];
    red[e] = pooled; __syncthreads();
    for (int st = 128; st > 0; st >>= 1) { if (e < st) red[e] += red[e + st]; __syncthreads(); }
    float mean = red[0] * (1.f / EMB_);
    __syncthreads();
    float d = pooled - mean;
    red[e] = d * d; __syncthreads();
    for (int st = 128; st > 0; st >>= 1) { if (e < st) red[e] += red[e + st]; __syncthreads(); }
    float var = red[0] * (1.f / EMB_);
    __syncthreads();
    float nv = d * rsqrtf(var + 1e-5f) * g[e] + bb[e];
    red[e] = nv * Wc[e * 2 + 0]; __syncthreads();
    for (int st = 128; st > 0; st >>= 1) { if (e < st) red[e] += red[e + st]; __syncthreads(); }
    float l0 = red[0] + bc[0];
    __syncthreads();
    red[e] = nv * Wc[e * 2 + 1]; __syncthreads();
    for (int st = 128; st > 0; st >>= 1) { if (e < st) red[e] += red[e + st]; __syncthreads(); }
    float l1 = red[0] + bc[1];
    if (e == 0) {
        float mx = fmaxf(l0, l1);
        float lse = mx + logf(expf(l0 - mx) + expf(l1 - mx));
        out[b * 2 + 0] = l0 - lse;
        out[b * 2 + 1] = l1 - lse;
    }
}

// ---------------- launch ------------------------------------------------------
extern "C" void kernel_launch(void* const* d_in, const int* in_sizes, int n_in,
                              void* d_out, int out_size) {
    const float* x     = (const float*)d_in[0];
    const float* W1    = (const float*)d_in[1];
    const float* b1    = (const float*)d_in[2];
    const float* cls1  = (const float*)d_in[3];
    const float* W2    = (const float*)d_in[4];
    const float* b2    = (const float*)d_in[5];
    const float* cls2  = (const float*)d_in[6];
    const float* ln1_g = (const float*)d_in[7];
    const float* ln1_b = (const float*)d_in[8];
    const float* Wq    = (const float*)d_in[9];
    const float* bq    = (const float*)d_in[10];
    const float* Wk    = (const float*)d_in[11];
    const float* bk    = (const float*)d_in[12];
    const float* Wv    = (const float*)d_in[13];
    const float* bv    = (const float*)d_in[14];
    const float* Wp    = (const float*)d_in[15];
    const float* bp    = (const float*)d_in[16];
    const float* ln2_g = (const float*)d_in[17];
    const float* ln2_b = (const float*)d_in[18];
    const float* lnc_g = (const float*)d_in[19];
    const float* lnc_b = (const float*)d_in[20];
    const float* Wc    = (const float*)d_in[21];
    const float* bc    = (const float*)d_in[22];
    float* out = (float*)d_out;

    static int inited = 0;
    if (!inited) {
        cudaFuncSetAttribute(gemm_nn, cudaFuncAttributeMaxDynamicSharedMemorySize, SMEM_NN);
        cudaFuncSetAttribute(gemm_nt, cudaFuncAttributeMaxDynamicSharedMemorySize, SMEM_NT);
        inited = 1;
    }

    float *T1, *T2, *Wt, *z, *h, *q, *k, *v, *S, *o;
    cudaGetSymbolAddress((void**)&T1, g_T1);
    cudaGetSymbolAddress((void**)&T2, g_T2);
    cudaGetSymbolAddress((void**)&Wt, g_Wt);
    cudaGetSymbolAddress((void**)&z,  g_z);
    cudaGetSymbolAddress((void**)&h,  g_h);
    cudaGetSymbolAddress((void**)&q,  g_q);
    cudaGetSymbolAddress((void**)&k,  g_k);
    cudaGetSymbolAddress((void**)&v,  g_v);
    cudaGetSymbolAddress((void**)&S,  g_S);
    cudaGetSymbolAddress((void**)&o,  g_o);

    prep_w<<<507904 / 256, 256>>>(W1, W2, Wq, Wk, Wv, Wp, Wt);
    im2col1<<<dim3(196, B_), 256>>>(x, T1);
    im2col2<<<dim3(196, B_), 192>>>(x, T2);
    cls_fill<<<B_, 256>>>(cls1, cls2, z);

    gemm_nn<<<dim3(2, 196), 256, SMEM_NN>>>(T1, Wt + OFF_W1, b1, z, MPE, 256, 768, 768, 1);
    gemm_nn<<<dim3(2, 196), 256, SMEM_NN>>>(T2, Wt + OFF_W2, b2, z, MPE, 256, 192, 192, 2);

    ln_kernel<<<MTOK, 256>>>(z, ln1_g, ln1_b, h, nullptr, 1);

    gemm_nn<<<dim3(2, 394), 256, SMEM_NN>>>(h, Wt + OFF_WQ, bq, q, MTOK, 256, 256, 256, 3);
    gemm_nn<<<dim3(2, 394), 256, SMEM_NN>>>(h, Wt + OFF_WK, bk, k, MTOK, 256, 256, 256, 3);
    gemm_nn<<<dim3(2, 394), 256, SMEM_NN>>>(h, Wt + OFF_WV, bv, v, MTOK, 256, 256, 256, 3);

    gemm_nt<<<dim3(4, 4, 256), 256, SMEM_NT>>>(q, k, S);
    softmax_div<<<dim3(394, 256), 128>>>(S);
    gemm_nn<<<dim3(1, 4, 256), 256, SMEM_NN>>>(S, v, nullptr, o, 394, 128, SP, 394, 4);

    gemm_nn<<<dim3(2, 394), 256, SMEM_NN>>>(o, Wt + OFF_WP, bp, h, MTOK, 256, 256, 256, 0);
    ln_kernel<<<MTOK, 256>>>(h, ln2_g, ln2_b, z, z, 0);

    head_kernel<<<B_, 256>>>(z, lnc_g, lnc_b, Wc, bc, out);
}